// round 2
// baseline (speedup 1.0000x reference)
#include <cuda_runtime.h>

#define B_GRAPHS 512
#define NPG 256
#define EPG 4096
#define NTOT (B_GRAPHS * NPG)      /* 131072 */
#define ETOT (B_GRAPHS * EPG)      /* 2097152 */
#define FIN 128
#define HD  64
#define TCLS 18
#define KTOP 16
#define DLAT 257

/* shared memory layout (byte offsets) */
#define OFF_CSR    0        /* 4096 * u16 = 8192                 */
#define OFF_ROWPTR 8192     /* 257 * i32 -> pad to 9232          */
#define OFF_CURSOR 9232     /* 256 * i32                          */
#define OFF_HIST   10256    /* 256 * i32                          */
#define OFF_INVDEG 11280    /* 256 * f32                          */
#define OFF_WTMP   12304    /* 16 * i32                           */
#define OFF_TOPK   12368    /* 16 * i32                           */
#define OFF_S5     12432    /* 256 * f32                          */
#define OFF_RED    13456    /* 256 * u64 = 2048                   */
#define OFF_HEAD   15504    /* head scratch (<= 2288 B)           */
#define OFF_W      17792    /* 128*64 f32 = 32768                 */
#define OFF_H      50560    /* 256*65 f32 = 66560                 */
#define OFF_L      117120   /* 256*65 f32 = 66560                 */
#define SMEM_BYTES 183680

/* spill for hidden layers 1..3 (layer 4 stays in SMEM, layer 5 is scalar) */
__device__ float g_hidden[(size_t)3 * NTOT * HD];   /* 96 MB */

struct Params {
    const float* __restrict__ x;
    const int*   __restrict__ ei;
    const float* __restrict__ w0; const float* __restrict__ b0;
    const float* __restrict__ w1; const float* __restrict__ b1;
    const float* __restrict__ w2; const float* __restrict__ b2;
    const float* __restrict__ w3; const float* __restrict__ b3;
    const float* __restrict__ w4; const float* __restrict__ b4;
    const float* __restrict__ c1w; const float* __restrict__ c1b;
    const float* __restrict__ c2w; const float* __restrict__ c2b;
    const float* __restrict__ d1w; const float* __restrict__ d1b;
    const float* __restrict__ d2w; const float* __restrict__ d2b;
    float* __restrict__ out;
    int out_size;
};

__global__ __launch_bounds__(256, 1) void dgcnn_kernel(Params p) {
    extern __shared__ unsigned char smem[];
    unsigned short*     csr    = (unsigned short*)(smem + OFF_CSR);
    int*                rowptr = (int*)(smem + OFF_ROWPTR);
    int*                cursor = (int*)(smem + OFF_CURSOR);
    int*                hist   = (int*)(smem + OFF_HIST);
    float*              invdeg = (float*)(smem + OFF_INVDEG);
    int*                wtmp   = (int*)(smem + OFF_WTMP);
    int*                topk   = (int*)(smem + OFF_TOPK);
    float*              S5     = (float*)(smem + OFF_S5);
    unsigned long long* red    = (unsigned long long*)(smem + OFF_RED);
    float*              c1s    = (float*)(smem + OFF_HEAD);
    float*              p1s    = c1s + 256;
    float*              flat   = p1s + 128;
    float*              lasts  = flat + 128;
    float*              outs   = lasts + 32;
    float*              lsev   = outs + 20;
    float*              Wt     = (float*)(smem + OFF_W);
    float*              Hs     = (float*)(smem + OFF_H);
    float*              Ls     = (float*)(smem + OFF_L);

    const int g     = blockIdx.x;
    const int t     = threadIdx.x;
    const int lane  = t & 31;
    const int warp  = t >> 5;
    const int nbase = g * NPG;
    const int ebase = g * EPG;
    const int* __restrict__ srcp = p.ei;
    const int* __restrict__ dstp = p.ei + ETOT;

    /* ---------------- per-graph CSR + degree (built once, reused 5x) ------- */
    hist[t]   = 0;
    cursor[t] = 0;                         /* cursor used as out-degree temp */
    __syncthreads();
    for (int e = t; e < EPG; e += 256) {
        int s = srcp[ebase + e] - nbase;
        int d = dstp[ebase + e] - nbase;
        atomicAdd(&hist[d], 1);
        atomicAdd(&cursor[s], 1);
    }
    __syncthreads();
    invdeg[t] = 1.0f / (float)(cursor[t] + 1);   /* +1 for self-loop */

    /* exclusive scan of hist -> rowptr */
    int hv  = hist[t];
    int inc = hv;
    #pragma unroll
    for (int o = 1; o < 32; o <<= 1) {
        int v = __shfl_up_sync(0xFFFFFFFFu, inc, o);
        if (lane >= o) inc += v;
    }
    if (lane == 31) wtmp[warp] = inc;
    __syncthreads();
    if (t == 0) {
        int a = 0;
        for (int w = 0; w < 8; w++) { int tv = wtmp[w]; wtmp[8 + w] = a; a += tv; }
    }
    __syncthreads();
    int rp = inc - hv + wtmp[8 + warp];
    rowptr[t] = rp;
    if (t == 0) rowptr[256] = EPG;
    cursor[t] = rp;
    __syncthreads();
    for (int e = t; e < EPG; e += 256) {
        int s = srcp[ebase + e] - nbase;
        int d = dstp[ebase + e] - nbase;
        int pos = atomicAdd(&cursor[d], 1);
        csr[pos] = (unsigned short)s;
    }
    __syncthreads();

    /* ---------------- 4 GCN layers with 64-wide output -------------------- */
    const int r0 = (t >> 2) << 2;      /* 4-node tile   */
    const int c0 = (t & 3) << 4;       /* 16-channel tile */

    for (int layer = 0; layer < 4; layer++) {
        const int Cin = (layer == 0) ? FIN : HD;
        const float* __restrict__ wptr;
        const float* __restrict__ bptr;
        switch (layer) {
            case 0:  wptr = p.w0; bptr = p.b0; break;
            case 1:  wptr = p.w1; bptr = p.b1; break;
            case 2:  wptr = p.w2; bptr = p.b2; break;
            default: wptr = p.w3; bptr = p.b3; break;
        }
        /* load W transposed: Wt[k][o] = w[o][k] */
        for (int idx = t; idx < Cin * HD; idx += 256) {
            int o = idx & 63, k = idx >> 6;
            Wt[k * 64 + o] = wptr[o * Cin + k];
        }

        float acc[4][16];
        #pragma unroll
        for (int i = 0; i < 4; i++)
            #pragma unroll
            for (int j = 0; j < 16; j++) acc[i][j] = 0.0f;

        if (layer == 0) {
            for (int half = 0; half < 2; half++) {
                __syncthreads();      /* Wt ready / previous chunk consumed */
                for (int idx = t; idx < NPG * 64; idx += 256) {
                    int r = idx >> 6, c = idx & 63;
                    Hs[r * 65 + c] = p.x[(nbase + r) * FIN + half * 64 + c];
                }
                __syncthreads();
                const float* wb = Wt + half * 64 * 64;
                #pragma unroll 4
                for (int k = 0; k < 64; k++) {
                    float a0 = Hs[(r0 + 0) * 65 + k];
                    float a1 = Hs[(r0 + 1) * 65 + k];
                    float a2 = Hs[(r0 + 2) * 65 + k];
                    float a3 = Hs[(r0 + 3) * 65 + k];
                    const float4* bp = (const float4*)(wb + k * 64 + c0);
                    float4 q0 = bp[0], q1 = bp[1], q2 = bp[2], q3 = bp[3];
                    float bv[16] = {q0.x,q0.y,q0.z,q0.w, q1.x,q1.y,q1.z,q1.w,
                                    q2.x,q2.y,q2.z,q2.w, q3.x,q3.y,q3.z,q3.w};
                    #pragma unroll
                    for (int j = 0; j < 16; j++) {
                        acc[0][j] += a0 * bv[j];
                        acc[1][j] += a1 * bv[j];
                        acc[2][j] += a2 * bv[j];
                        acc[3][j] += a3 * bv[j];
                    }
                }
            }
        } else {
            __syncthreads();          /* Wt ready, Hs from previous layer final */
            #pragma unroll 4
            for (int k = 0; k < 64; k++) {
                float a0 = Hs[(r0 + 0) * 65 + k];
                float a1 = Hs[(r0 + 1) * 65 + k];
                float a2 = Hs[(r0 + 2) * 65 + k];
                float a3 = Hs[(r0 + 3) * 65 + k];
                const float4* bp = (const float4*)(Wt + k * 64 + c0);
                float4 q0 = bp[0], q1 = bp[1], q2 = bp[2], q3 = bp[3];
                float bv[16] = {q0.x,q0.y,q0.z,q0.w, q1.x,q1.y,q1.z,q1.w,
                                q2.x,q2.y,q2.z,q2.w, q3.x,q3.y,q3.z,q3.w};
                #pragma unroll
                for (int j = 0; j < 16; j++) {
                    acc[0][j] += a0 * bv[j];
                    acc[1][j] += a1 * bv[j];
                    acc[2][j] += a2 * bv[j];
                    acc[3][j] += a3 * bv[j];
                }
            }
        }

        /* bias + store h_lin to Ls */
        #pragma unroll
        for (int j = 0; j < 16; j++) {
            float bj = __ldg(&bptr[c0 + j]);
            #pragma unroll
            for (int i = 0; i < 4; i++)
                Ls[(r0 + i) * 65 + c0 + j] = acc[i][j] + bj;
        }
        __syncthreads();

        /* aggregation: warp per destination node, lanes own 2 channels */
        float* __restrict__ gh = g_hidden + (size_t)layer * NTOT * HD;
        for (int d = warp; d < NPG; d += 8) {
            float a0 = Ls[d * 65 + lane];        /* self-loop contribution */
            float a1 = Ls[d * 65 + 32 + lane];
            int e1 = rowptr[d + 1];
            for (int e = rowptr[d]; e < e1; e++) {
                int s = csr[e];
                a0 += Ls[s * 65 + lane];
                a1 += Ls[s * 65 + 32 + lane];
            }
            float sc = invdeg[d];
            float h0 = tanhf(a0 * sc);
            float h1 = tanhf(a1 * sc);
            Hs[d * 65 + lane]      = h0;
            Hs[d * 65 + 32 + lane] = h1;
            if (layer < 3) {
                size_t gb = (size_t)(nbase + d) * HD;
                gh[gb + lane]      = h0;
                gh[gb + 32 + lane] = h1;
            }
        }
        __syncthreads();
    }

    /* ---------------- layer 5: 64 -> 1 ------------------------------------ */
    if (t < 64) Wt[t] = p.w4[t];
    __syncthreads();
    {
        float a4 = __ldg(&p.b4[0]);
        #pragma unroll 8
        for (int k = 0; k < 64; k++) a4 += Hs[t * 65 + k] * Wt[k];
        Ls[t] = a4;
    }
    __syncthreads();
    {
        float a = Ls[t];
        int e1 = rowptr[t + 1];
        for (int e = rowptr[t]; e < e1; e++) a += Ls[csr[e]];
        S5[t] = tanhf(a * invdeg[t]);
    }
    __syncthreads();

    /* ---------------- top-16 selection (stable, ties -> lower index) ------ */
    {
        unsigned u = __float_as_uint(S5[t]);
        u = (u & 0x80000000u) ? ~u : (u | 0x80000000u);
        bool taken = false;
        for (int r = 0; r < KTOP; r++) {
            unsigned long long key =
                taken ? 0ull
                      : (((unsigned long long)u << 32) | (unsigned)(NPG - 1 - t));
            red[t] = key;
            __syncthreads();
            #pragma unroll
            for (int s = 128; s >= 1; s >>= 1) {
                if (t < s) {
                    unsigned long long o = red[t + s];
                    if (o > red[t]) red[t] = o;
                }
                __syncthreads();
            }
            int node = NPG - 1 - (int)(red[0] & 0xFFFFFFFFu);
            if (t == node) taken = true;
            if (t == 0) topk[r] = node;
            __syncthreads();
        }
    }

    /* ---------------- gather feat rows [16 x 257] into Ls ----------------- */
    float* Fs = Ls;
    for (int idx = t; idx < KTOP * DLAT; idx += 256) {
        int l = idx / DLAT;
        int d = idx - l * DLAT;
        int node = topk[l];
        float v;
        if (d < 192) {
            v = g_hidden[((size_t)(d >> 6) * NTOT + (nbase + node)) * HD + (d & 63)];
        } else if (d < 256) {
            v = Hs[node * 65 + (d - 192)];       /* h4 kept in SMEM */
        } else {
            v = S5[node];                        /* h5 */
        }
        Fs[l * DLAT + d] = v;
    }
    __syncthreads();

    /* ---------------- conv1 (per-slot matmul 257 -> 16) + relu ------------ */
    {
        int o = t >> 4, l = t & 15;
        float acc = __ldg(&p.c1b[o]);
        const float* wr = p.c1w + o * DLAT;
        const float* fr = Fs + l * DLAT;
        for (int d = 0; d < DLAT; d++) acc += fr[d] * __ldg(&wr[d]);
        c1s[o * 16 + l] = fmaxf(acc, 0.0f);
    }
    __syncthreads();
    /* maxpool(2,2): [16,16] -> [16,8] */
    if (t < 128) {
        int o = t >> 3, m = t & 7;
        p1s[o * 8 + m] = fmaxf(c1s[o * 16 + 2 * m], c1s[o * 16 + 2 * m + 1]);
    }
    __syncthreads();
    /* conv2: 16ch x k5 -> 32ch, 4 positions, relu */
    if (t < 128) {
        int oc = t >> 2, pp = t & 3;
        float acc = __ldg(&p.c2b[oc]);
        const float* wr = p.c2w + oc * 80;
        #pragma unroll
        for (int ic = 0; ic < 16; ic++)
            #pragma unroll
            for (int kk = 0; kk < 5; kk++)
                acc += p1s[ic * 8 + pp + kk] * __ldg(&wr[ic * 5 + kk]);
        flat[oc * 4 + pp] = fmaxf(acc, 0.0f);
    }
    __syncthreads();
    /* dense1: 128 -> 32, relu   (third output: 'last') */
    if (t < 32) {
        float acc = __ldg(&p.d1b[t]);
        const float* wr = p.d1w + t * 128;
        #pragma unroll 8
        for (int i = 0; i < 128; i++) acc += flat[i] * __ldg(&wr[i]);
        float lv = fmaxf(acc, 0.0f);
        lasts[t] = lv;
        if (p.out_size >= 2 * B_GRAPHS * TCLS + B_GRAPHS * 32)
            p.out[2 * B_GRAPHS * TCLS + g * 32 + t] = lv;
    }
    __syncthreads();
    /* dense2: 32 -> 18  (second output: logits) */
    if (t < TCLS) {
        float acc = __ldg(&p.d2b[t]);
        const float* wr = p.d2w + t * 32;
        #pragma unroll
        for (int j = 0; j < 32; j++) acc += lasts[j] * __ldg(&wr[j]);
        outs[t] = acc;
        if (p.out_size >= 2 * B_GRAPHS * TCLS)
            p.out[B_GRAPHS * TCLS + g * TCLS + t] = acc;
    }
    __syncthreads();
    if (t == 0) {
        float m = -1e30f;
        for (int j = 0; j < TCLS; j++) m = fmaxf(m, outs[j]);
        float s = 0.0f;
        for (int j = 0; j < TCLS; j++) s += expf(outs[j] - m);
        lsev[0] = m + logf(s);
    }
    __syncthreads();
    /* first output: log_softmax */
    if (t < TCLS) p.out[g * TCLS + t] = outs[t] - lsev[0];
}

extern "C" void kernel_launch(void* const* d_in, const int* in_sizes, int n_in,
                              void* d_out, int out_size) {
    /* input order: x, edge_index, batch, [num_graphs], w0,b0..w4,b4,
       conv1_w, conv1_b, conv2_w, conv2_b, d1_w, d1_b, d2_w, d2_b.
       num_graphs (scalar) may or may not be materialized — detect via size. */
    int bi = 4;
    if (n_in >= 4 && in_sizes[3] != 1) bi = 3;

    Params p;
    p.x   = (const float*)d_in[0];
    p.ei  = (const int*)d_in[1];
    p.w0  = (const float*)d_in[bi + 0];  p.b0 = (const float*)d_in[bi + 1];
    p.w1  = (const float*)d_in[bi + 2];  p.b1 = (const float*)d_in[bi + 3];
    p.w2  = (const float*)d_in[bi + 4];  p.b2 = (const float*)d_in[bi + 5];
    p.w3  = (const float*)d_in[bi + 6];  p.b3 = (const float*)d_in[bi + 7];
    p.w4  = (const float*)d_in[bi + 8];  p.b4 = (const float*)d_in[bi + 9];
    p.c1w = (const float*)d_in[bi + 10]; p.c1b = (const float*)d_in[bi + 11];
    p.c2w = (const float*)d_in[bi + 12]; p.c2b = (const float*)d_in[bi + 13];
    p.d1w = (const float*)d_in[bi + 14]; p.d1b = (const float*)d_in[bi + 15];
    p.d2w = (const float*)d_in[bi + 16]; p.d2b = (const float*)d_in[bi + 17];
    p.out = (float*)d_out;
    p.out_size = out_size;

    cudaFuncSetAttribute(dgcnn_kernel,
                         cudaFuncAttributeMaxDynamicSharedMemorySize, SMEM_BYTES);
    dgcnn_kernel<<<B_GRAPHS, 256, SMEM_BYTES>>>(p);
}

// round 5
// speedup vs baseline: 1.3176x; 1.3176x over previous
#include <cuda_runtime.h>

#define B_GRAPHS 512
#define NPG 256
#define EPG 4096
#define NTOT (B_GRAPHS * NPG)      /* 131072 */
#define ETOT (B_GRAPHS * EPG)      /* 2097152 */
#define FIN 128
#define HD  64
#define TCLS 18
#define KTOP 16
#define DLAT 257
#define NTHREADS 512
#define WSTRIDE 68                  /* Wt row stride (floats): float4-aligned */
#define HSTRIDE 68                  /* Hs/Ls row stride (floats): float4-aligned rows */

/* shared memory layout (byte offsets) */
#define OFF_CSR    0        /* 4096 * u16 = 8192                 */
#define OFF_ROWPTR 8192     /* 257 * i32 -> pad to 9232          */
#define OFF_CURSOR 9232     /* 256 * i32                          */
#define OFF_HIST   10256    /* 256 * i32                          */
#define OFF_INVDEG 11280    /* 256 * f32                          */
#define OFF_WTMP   12304    /* 16 * i32                           */
#define OFF_TOPK   12368    /* 16 * i32                           */
#define OFF_S5     12432    /* 256 * f32                          */
#define OFF_RED    13456    /* 256 * u64 = 2048                   */
#define OFF_HEAD   15504    /* head scratch                       */
#define OFF_W      17792    /* 128*68 f32 = 34816                 */
#define OFF_H      52608    /* 256*68 f32 = 69632                 */
#define OFF_L      122240   /* 256*68 f32 = 69632                 */
#define SMEM_BYTES 191872

/* spill for hidden layers 1..3 (layer 4 stays in SMEM, layer 5 is scalar) */
__device__ float g_hidden[(size_t)3 * NTOT * HD];   /* 96 MB */

struct Params {
    const float* __restrict__ x;
    const int*   __restrict__ ei;
    const float* __restrict__ w0; const float* __restrict__ b0;
    const float* __restrict__ w1; const float* __restrict__ b1;
    const float* __restrict__ w2; const float* __restrict__ b2;
    const float* __restrict__ w3; const float* __restrict__ b3;
    const float* __restrict__ w4; const float* __restrict__ b4;
    const float* __restrict__ c1w; const float* __restrict__ c1b;
    const float* __restrict__ c2w; const float* __restrict__ c2b;
    const float* __restrict__ d1w; const float* __restrict__ d1b;
    const float* __restrict__ d2w; const float* __restrict__ d2b;
    float* __restrict__ out;
    int out_size;
};

__global__ __launch_bounds__(NTHREADS, 1) void dgcnn_kernel(Params p) {
    extern __shared__ unsigned char smem[];
    unsigned short*     csr    = (unsigned short*)(smem + OFF_CSR);
    int*                rowptr = (int*)(smem + OFF_ROWPTR);
    int*                cursor = (int*)(smem + OFF_CURSOR);
    int*                hist   = (int*)(smem + OFF_HIST);
    float*              invdeg = (float*)(smem + OFF_INVDEG);
    int*                wtmp   = (int*)(smem + OFF_WTMP);
    int*                topk   = (int*)(smem + OFF_TOPK);
    float*              S5     = (float*)(smem + OFF_S5);
    unsigned long long* red    = (unsigned long long*)(smem + OFF_RED);
    float*              c1s    = (float*)(smem + OFF_HEAD);
    float*              p1s    = c1s + 256;
    float*              flat   = p1s + 128;
    float*              lasts  = flat + 128;
    float*              outs   = lasts + 32;
    float*              lsev   = outs + 20;
    float*              Wt     = (float*)(smem + OFF_W);
    float*              Hs     = (float*)(smem + OFF_H);
    float*              Ls     = (float*)(smem + OFF_L);

    const int g     = blockIdx.x;
    const int t     = threadIdx.x;
    const int lane  = t & 31;
    const int warp  = t >> 5;
    const int nbase = g * NPG;
    const int ebase = g * EPG;
    const int* __restrict__ srcp = p.ei;
    const int* __restrict__ dstp = p.ei + ETOT;

    /* ---------------- per-graph CSR + degree (built once, reused 5x) ------- */
    if (t < 256) { hist[t] = 0; cursor[t] = 0; }
    __syncthreads();
    for (int e = t; e < EPG; e += NTHREADS) {
        int s = srcp[ebase + e] - nbase;
        int d = dstp[ebase + e] - nbase;
        atomicAdd(&hist[d], 1);
        atomicAdd(&cursor[s], 1);
    }
    __syncthreads();
    if (t < 256) invdeg[t] = 1.0f / (float)(cursor[t] + 1);  /* +1 self-loop */

    /* exclusive scan of hist -> rowptr (first 8 warps) */
    if (t < 256) {
        int hv  = hist[t];
        int inc = hv;
        #pragma unroll
        for (int o = 1; o < 32; o <<= 1) {
            int v = __shfl_up_sync(0xFFFFFFFFu, inc, o);
            if (lane >= o) inc += v;
        }
        if (lane == 31) wtmp[warp] = inc;
        __syncwarp();
        hist[t] = inc - hv;   /* intra-warp exclusive */
    }
    __syncthreads();
    if (t == 0) {
        int a = 0;
        for (int w = 0; w < 8; w++) { int tv = wtmp[w]; wtmp[8 + w] = a; a += tv; }
    }
    __syncthreads();
    if (t < 256) {
        int rp = hist[t] + wtmp[8 + warp];
        rowptr[t] = rp;
        cursor[t] = rp;
        if (t == 0) rowptr[256] = EPG;
    }
    __syncthreads();
    for (int e = t; e < EPG; e += NTHREADS) {
        int s = srcp[ebase + e] - nbase;
        int d = dstp[ebase + e] - nbase;
        int pos = atomicAdd(&cursor[d], 1);
        csr[pos] = (unsigned short)s;
    }
    __syncthreads();

    /* ---------------- 4 GCN layers, 64-wide output ------------------------- */
    /* thread tile: 4 rows x 8 cols  (64 row-groups x 8 col-groups = 512)     */
    const int r0 = (t >> 3) << 2;     /* 0..252 step 4 */
    const int c0 = (t & 7) << 3;      /* 0..56  step 8 */

    for (int layer = 0; layer < 4; layer++) {
        const int Cin = (layer == 0) ? FIN : HD;
        const float* __restrict__ wptr;
        const float* __restrict__ bptr;
        switch (layer) {
            case 0:  wptr = p.w0; bptr = p.b0; break;
            case 1:  wptr = p.w1; bptr = p.b1; break;
            case 2:  wptr = p.w2; bptr = p.b2; break;
            default: wptr = p.w3; bptr = p.b3; break;
        }
        /* stage W transposed: Wt[k][o] = w[o][k]; coalesced global reads */
        for (int idx = t; idx < Cin * HD; idx += NTHREADS) {
            int o = idx / Cin, k = idx - o * Cin;     /* consecutive idx -> consecutive k */
            Wt[k * WSTRIDE + o] = wptr[idx];
        }

        float acc[4][8];
        #pragma unroll
        for (int i = 0; i < 4; i++)
            #pragma unroll
            for (int j = 0; j < 8; j++) acc[i][j] = 0.0f;

        const int nhalf = (layer == 0) ? 2 : 1;
        for (int half = 0; half < nhalf; half++) {
            if (layer == 0) {
                __syncthreads();   /* Wt ready / previous chunk consumed */
                for (int idx = t; idx < NPG * 16; idx += NTHREADS) {
                    int r = idx >> 4, cb = (idx & 15) << 2;
                    float4 v = *(const float4*)&p.x[(nbase + r) * FIN + half * 64 + cb];
                    *(float4*)&Hs[r * HSTRIDE + cb] = v;   /* row stride 272B: aligned */
                }
            }
            __syncthreads();       /* Wt + Hs ready */
            const float* wb = Wt + half * 64 * WSTRIDE;
            #pragma unroll 2
            for (int k4 = 0; k4 < 64; k4 += 4) {
                float4 a0 = *(const float4*)&Hs[(r0 + 0) * HSTRIDE + k4];
                float4 a1 = *(const float4*)&Hs[(r0 + 1) * HSTRIDE + k4];
                float4 a2 = *(const float4*)&Hs[(r0 + 2) * HSTRIDE + k4];
                float4 a3 = *(const float4*)&Hs[(r0 + 3) * HSTRIDE + k4];
                float ar[4][4] = {{a0.x,a0.y,a0.z,a0.w},{a1.x,a1.y,a1.z,a1.w},
                                  {a2.x,a2.y,a2.z,a2.w},{a3.x,a3.y,a3.z,a3.w}};
                #pragma unroll
                for (int kk = 0; kk < 4; kk++) {
                    const float4* bp = (const float4*)(wb + (k4 + kk) * WSTRIDE + c0);
                    float4 b0 = bp[0], b1 = bp[1];
                    float bv[8] = {b0.x,b0.y,b0.z,b0.w, b1.x,b1.y,b1.z,b1.w};
                    #pragma unroll
                    for (int i = 0; i < 4; i++) {
                        float av = ar[i][kk];
                        #pragma unroll
                        for (int j = 0; j < 8; j++) acc[i][j] += av * bv[j];
                    }
                }
            }
        }

        /* bias + store h_lin to Ls */
        #pragma unroll
        for (int j = 0; j < 8; j++) {
            float bj = __ldg(&bptr[c0 + j]);
            #pragma unroll
            for (int i = 0; i < 4; i++)
                Ls[(r0 + i) * HSTRIDE + c0 + j] = acc[i][j] + bj;
        }
        __syncthreads();

        /* aggregation: warp per destination node, lanes own 2 channels */
        float* __restrict__ gh = g_hidden + (size_t)layer * NTOT * HD;
        for (int d = warp; d < NPG; d += 16) {
            float aA = Ls[d * HSTRIDE + lane];        /* self-loop contribution */
            float aB = Ls[d * HSTRIDE + 32 + lane];
            int e1 = rowptr[d + 1];
            for (int e = rowptr[d]; e < e1; e++) {
                int s = csr[e];
                aA += Ls[s * HSTRIDE + lane];
                aB += Ls[s * HSTRIDE + 32 + lane];
            }
            float sc = invdeg[d];
            float h0 = tanhf(aA * sc);
            float h1 = tanhf(aB * sc);
            Hs[d * HSTRIDE + lane]      = h0;
            Hs[d * HSTRIDE + 32 + lane] = h1;
            if (layer < 3) {
                size_t gb = (size_t)(nbase + d) * HD;
                gh[gb + lane]      = h0;
                gh[gb + 32 + lane] = h1;
            }
        }
        __syncthreads();
    }

    /* ---------------- layer 5: 64 -> 1 ------------------------------------ */
    if (t < 64) Wt[t] = p.w4[t];
    __syncthreads();
    if (t < 256) {
        float a4 = __ldg(&p.b4[0]);
        #pragma unroll 8
        for (int k = 0; k < 64; k++) a4 += Hs[t * HSTRIDE + k] * Wt[k];
        Ls[t] = a4;
    }
    __syncthreads();
    if (t < 256) {
        float a = Ls[t];
        int e1 = rowptr[t + 1];
        for (int e = rowptr[t]; e < e1; e++) a += Ls[csr[e]];
        S5[t] = tanhf(a * invdeg[t]);
    }
    __syncthreads();

    /* ---------------- top-16 selection (stable, ties -> lower index) ------ */
    {
        unsigned u = 0;
        if (t < 256) {
            u = __float_as_uint(S5[t]);
            u = (u & 0x80000000u) ? ~u : (u | 0x80000000u);
        }
        bool taken = false;
        for (int r = 0; r < KTOP; r++) {
            if (t < 256) {
                red[t] = taken ? 0ull
                    : (((unsigned long long)u << 32) | (unsigned)(NPG - 1 - t));
            }
            __syncthreads();
            #pragma unroll
            for (int s = 128; s >= 1; s >>= 1) {
                if (t < s) {
                    unsigned long long o = red[t + s];
                    if (o > red[t]) red[t] = o;
                }
                __syncthreads();
            }
            int node = NPG - 1 - (int)(red[0] & 0xFFFFFFFFu);
            if (t == node) taken = true;
            if (t == 0) topk[r] = node;
            __syncthreads();
        }
    }

    /* ---------------- gather feat rows [16 x 257] into Ls ----------------- */
    float* Fs = Ls;
    for (int idx = t; idx < KTOP * DLAT; idx += NTHREADS) {
        int l = idx / DLAT;
        int d = idx - l * DLAT;
        int node = topk[l];
        float v;
        if (d < 192) {
            v = g_hidden[((size_t)(d >> 6) * NTOT + (nbase + node)) * HD + (d & 63)];
        } else if (d < 256) {
            v = Hs[node * HSTRIDE + (d - 192)];   /* h4 kept in SMEM */
        } else {
            v = S5[node];                         /* h5 */
        }
        Fs[l * DLAT + d] = v;
    }
    __syncthreads();

    /* ---------------- conv1 (per-slot matmul 257 -> 16) + relu ------------ */
    if (t < 256) {
        int o = t >> 4, l = t & 15;
        float acc = __ldg(&p.c1b[o]);
        const float* wr = p.c1w + o * DLAT;
        const float* fr = Fs + l * DLAT;
        for (int d = 0; d < DLAT; d++) acc += fr[d] * __ldg(&wr[d]);
        c1s[o * 16 + l] = fmaxf(acc, 0.0f);
    }
    __syncthreads();
    /* maxpool(2,2): [16,16] -> [16,8] */
    if (t < 128) {
        int o = t >> 3, m = t & 7;
        p1s[o * 8 + m] = fmaxf(c1s[o * 16 + 2 * m], c1s[o * 16 + 2 * m + 1]);
    }
    __syncthreads();
    /* conv2: 16ch x k5 -> 32ch, 4 positions, relu */
    if (t < 128) {
        int oc = t >> 2, pp = t & 3;
        float acc = __ldg(&p.c2b[oc]);
        const float* wr = p.c2w + oc * 80;
        #pragma unroll
        for (int ic = 0; ic < 16; ic++)
            #pragma unroll
            for (int kk = 0; kk < 5; kk++)
                acc += p1s[ic * 8 + pp + kk] * __ldg(&wr[ic * 5 + kk]);
        flat[oc * 4 + pp] = fmaxf(acc, 0.0f);
    }
    __syncthreads();
    /* dense1: 128 -> 32, relu   (third output: 'last') */
    if (t < 32) {
        float acc = __ldg(&p.d1b[t]);
        const float* wr = p.d1w + t * 128;
        #pragma unroll 8
        for (int i = 0; i < 128; i++) acc += flat[i] * __ldg(&wr[i]);
        float lv = fmaxf(acc, 0.0f);
        lasts[t] = lv;
        if (p.out_size >= 2 * B_GRAPHS * TCLS + B_GRAPHS * 32)
            p.out[2 * B_GRAPHS * TCLS + g * 32 + t] = lv;
    }
    __syncthreads();
    /* dense2: 32 -> 18  (second output: logits) */
    if (t < TCLS) {
        float acc = __ldg(&p.d2b[t]);
        const float* wr = p.d2w + t * 32;
        #pragma unroll
        for (int j = 0; j < 32; j++) acc += lasts[j] * __ldg(&wr[j]);
        outs[t] = acc;
        if (p.out_size >= 2 * B_GRAPHS * TCLS)
            p.out[B_GRAPHS * TCLS + g * TCLS + t] = acc;
    }
    __syncthreads();
    if (t == 0) {
        float m = -1e30f;
        for (int j = 0; j < TCLS; j++) m = fmaxf(m, outs[j]);
        float s = 0.0f;
        for (int j = 0; j < TCLS; j++) s += expf(outs[j] - m);
        lsev[0] = m + logf(s);
    }
    __syncthreads();
    /* first output: log_softmax */
    if (t < TCLS) p.out[g * TCLS + t] = outs[t] - lsev[0];
}

extern "C" void kernel_launch(void* const* d_in, const int* in_sizes, int n_in,
                              void* d_out, int out_size) {
    int bi = 4;
    if (n_in >= 4 && in_sizes[3] != 1) bi = 3;

    Params p;
    p.x   = (const float*)d_in[0];
    p.ei  = (const int*)d_in[1];
    p.w0  = (const float*)d_in[bi + 0];  p.b0 = (const float*)d_in[bi + 1];
    p.w1  = (const float*)d_in[bi + 2];  p.b1 = (const float*)d_in[bi + 3];
    p.w2  = (const float*)d_in[bi + 4];  p.b2 = (const float*)d_in[bi + 5];
    p.w3  = (const float*)d_in[bi + 6];  p.b3 = (const float*)d_in[bi + 7];
    p.w4  = (const float*)d_in[bi + 8];  p.b4 = (const float*)d_in[bi + 9];
    p.c1w = (const float*)d_in[bi + 10]; p.c1b = (const float*)d_in[bi + 11];
    p.c2w = (const float*)d_in[bi + 12]; p.c2b = (const float*)d_in[bi + 13];
    p.d1w = (const float*)d_in[bi + 14]; p.d1b = (const float*)d_in[bi + 15];
    p.d2w = (const float*)d_in[bi + 16]; p.d2b = (const float*)d_in[bi + 17];
    p.out = (float*)d_out;
    p.out_size = out_size;

    cudaFuncSetAttribute(dgcnn_kernel,
                         cudaFuncAttributeMaxDynamicSharedMemorySize, SMEM_BYTES);
    dgcnn_kernel<<<B_GRAPHS, NTHREADS, SMEM_BYTES>>>(p);
}